// round 1
// baseline (speedup 1.0000x reference)
#include <cuda_runtime.h>
#include <cuda_bf16.h>
#include <math.h>

// ---------------------------------------------------------------------------
// HermitianAttention  (B=2, S=2048, D=1024, H=16, hd=64)
//   qkv = complex linears; scores = Re(Q K^H) = Qr.Kr + Qi.Ki; softmax;
//   out = attn @ V (r,i); y = complex linear O.
// Round-0 baseline: fp32 SIMT tiled GEMMs + streaming flash attention.
// ---------------------------------------------------------------------------

#define BATCH   2
#define SEQ     2048
#define DIMM    1024
#define NH      16
#define HD      64
#define NTOK    (BATCH * SEQ)          // 4096
#define NTD     (NTOK * DIMM)          // 4194304
#define ATT_SCALE 0.125f               // HD^-0.5

// scratch: qr qi kr ki vr vi ar ai  (8 x 16MB = 128MB)
__device__ float g_scratch[8u * NTD];

// ---------------------------------------------------------------------------
// Fused complex GEMM:  Yr = Xr@Wr - Xi@Wi ;  Yi = Xr@Wi + Xi@Wr
// M=4096, K=1024, N=1024.  Tiles: BM=BN=64, BK=32; 256 threads, 4x4 microtile.
// ---------------------------------------------------------------------------
__global__ void __launch_bounds__(256, 2)
clinear_kernel(const float* __restrict__ Xr, const float* __restrict__ Xi,
               const float* __restrict__ Wr, const float* __restrict__ Wi,
               float* __restrict__ Yr, float* __restrict__ Yi)
{
    const int M = NTOK, K = DIMM, N = DIMM;
    (void)M;
    __shared__ float sXr[32][68], sXi[32][68];   // [k][m], padded
    __shared__ float sWr[32][64], sWi[32][64];   // [k][n]

    const int tid = threadIdx.x;
    const int bm = blockIdx.y * 64;
    const int bn = blockIdx.x * 64;
    const int tx = tid & 15, ty = tid >> 4;
    const int tr = ty * 4, tc = tx * 4;

    float aR[4][4] = {{0}}, aI[4][4] = {{0}};

    const int xr_row = tid >> 3;          // 0..31
    const int xr_k4  = (tid & 7) << 2;    // 0..28
    const int w_k    = tid >> 4;          // 0..15
    const int w_c4   = (tid & 15) << 2;   // 0..60

    for (int k0 = 0; k0 < K; k0 += 32) {
        #pragma unroll
        for (int p = 0; p < 2; p++) {
            int row = xr_row + p * 32;
            const float4 x4r = *(const float4*)(Xr + (size_t)(bm + row) * K + k0 + xr_k4);
            const float4 x4i = *(const float4*)(Xi + (size_t)(bm + row) * K + k0 + xr_k4);
            sXr[xr_k4 + 0][row] = x4r.x; sXr[xr_k4 + 1][row] = x4r.y;
            sXr[xr_k4 + 2][row] = x4r.z; sXr[xr_k4 + 3][row] = x4r.w;
            sXi[xr_k4 + 0][row] = x4i.x; sXi[xr_k4 + 1][row] = x4i.y;
            sXi[xr_k4 + 2][row] = x4i.z; sXi[xr_k4 + 3][row] = x4i.w;
        }
        #pragma unroll
        for (int p = 0; p < 2; p++) {
            int kk = w_k + p * 16;
            *(float4*)&sWr[kk][w_c4] = *(const float4*)(Wr + (size_t)(k0 + kk) * N + bn + w_c4);
            *(float4*)&sWi[kk][w_c4] = *(const float4*)(Wi + (size_t)(k0 + kk) * N + bn + w_c4);
        }
        __syncthreads();

        #pragma unroll
        for (int kk = 0; kk < 32; kk++) {
            const float4 x4r = *(const float4*)&sXr[kk][tr];
            const float4 x4i = *(const float4*)&sXi[kk][tr];
            const float4 w4r = *(const float4*)&sWr[kk][tc];
            const float4 w4i = *(const float4*)&sWi[kk][tc];
            const float xr_[4] = {x4r.x, x4r.y, x4r.z, x4r.w};
            const float xi_[4] = {x4i.x, x4i.y, x4i.z, x4i.w};
            const float wr_[4] = {w4r.x, w4r.y, w4r.z, w4r.w};
            const float wi_[4] = {w4i.x, w4i.y, w4i.z, w4i.w};
            #pragma unroll
            for (int i = 0; i < 4; i++) {
                #pragma unroll
                for (int j = 0; j < 4; j++) {
                    aR[i][j] = fmaf(xr_[i],  wr_[j], aR[i][j]);
                    aR[i][j] = fmaf(-xi_[i], wi_[j], aR[i][j]);
                    aI[i][j] = fmaf(xr_[i],  wi_[j], aI[i][j]);
                    aI[i][j] = fmaf(xi_[i],  wr_[j], aI[i][j]);
                }
            }
        }
        __syncthreads();
    }

    #pragma unroll
    for (int i = 0; i < 4; i++) {
        float4 r4 = make_float4(aR[i][0], aR[i][1], aR[i][2], aR[i][3]);
        float4 i4 = make_float4(aI[i][0], aI[i][1], aI[i][2], aI[i][3]);
        *(float4*)(Yr + (size_t)(bm + tr + i) * N + bn + tc) = r4;
        *(float4*)(Yi + (size_t)(bm + tr + i) * N + bn + tc) = i4;
    }
}

// ---------------------------------------------------------------------------
// Flash attention per (b, h, q-tile of 64): scores = Qr.Kr^T + Qi.Ki^T,
// online softmax, out_r/out_i accumulated in registers, written to merged
// [B,S,D] layout (head-merge free).
// ---------------------------------------------------------------------------
struct FlashSmem {
    float Qr[64][68], Qi[64][68];   // transposed: [d][q]
    float Kr[64][68], Ki[64][68];   // transposed: [d][k]
    float Vr[64][68], Vi[64][68];   // natural:   [k][d]
    float S [64][68];               // scores/probs [q][k]
    float M [64], L[64], A[64];
};

__global__ void __launch_bounds__(256, 1)
flash_kernel(const float* __restrict__ Qr, const float* __restrict__ Qi,
             const float* __restrict__ Kr, const float* __restrict__ Ki,
             const float* __restrict__ Vr, const float* __restrict__ Vi,
             float* __restrict__ Or, float* __restrict__ Oi)
{
    extern __shared__ char smem_raw[];
    FlashSmem& sm = *reinterpret_cast<FlashSmem*>(smem_raw);

    const int tid = threadIdx.x;
    const int qblk = blockIdx.x;              // 0..31
    const int bh   = blockIdx.y;              // 0..31
    const int b = bh >> 4, h = bh & 15;
    const size_t tok0 = (size_t)b * SEQ;
    const int col0 = h * HD;
    const int q0g  = qblk * 64;

    const int ldr  = tid >> 4;                // 0..15 (row group for loads)
    const int ldd4 = (tid & 15) << 2;         // 0..60

    // Load Q tile transposed
    #pragma unroll
    for (int p = 0; p < 4; p++) {
        int q = ldr + p * 16;
        size_t off = (tok0 + q0g + q) * DIMM + col0 + ldd4;
        float4 vr = *(const float4*)(Qr + off);
        sm.Qr[ldd4 + 0][q] = vr.x; sm.Qr[ldd4 + 1][q] = vr.y;
        sm.Qr[ldd4 + 2][q] = vr.z; sm.Qr[ldd4 + 3][q] = vr.w;
        float4 vi = *(const float4*)(Qi + off);
        sm.Qi[ldd4 + 0][q] = vi.x; sm.Qi[ldd4 + 1][q] = vi.y;
        sm.Qi[ldd4 + 2][q] = vi.z; sm.Qi[ldd4 + 3][q] = vi.w;
    }
    if (tid < 64) { sm.M[tid] = -1e30f; sm.L[tid] = 0.0f; }

    const int tx = tid & 15, ty = tid >> 4;
    const int qr0 = ty * 4;                   // rows (score & output phases)
    const int kc0 = tx * 4;                   // score cols
    const int dc0 = tx * 4;                   // output cols
    const int sq  = tid >> 2;                 // softmax row
    const int sc  = (tid & 3) * 16;           // softmax col start

    float oR[4][4] = {{0}}, oI[4][4] = {{0}};

    __syncthreads();

    for (int jt = 0; jt < SEQ / 64; jt++) {
        // ---- load K (transposed) and V (natural) tiles ----
        #pragma unroll
        for (int p = 0; p < 4; p++) {
            int k = ldr + p * 16;
            size_t off = (tok0 + (size_t)jt * 64 + k) * DIMM + col0 + ldd4;
            float4 vr = *(const float4*)(Kr + off);
            sm.Kr[ldd4 + 0][k] = vr.x; sm.Kr[ldd4 + 1][k] = vr.y;
            sm.Kr[ldd4 + 2][k] = vr.z; sm.Kr[ldd4 + 3][k] = vr.w;
            float4 vi = *(const float4*)(Ki + off);
            sm.Ki[ldd4 + 0][k] = vi.x; sm.Ki[ldd4 + 1][k] = vi.y;
            sm.Ki[ldd4 + 2][k] = vi.z; sm.Ki[ldd4 + 3][k] = vi.w;
            *(float4*)&sm.Vr[k][ldd4] = *(const float4*)(Vr + off);
            *(float4*)&sm.Vi[k][ldd4] = *(const float4*)(Vi + off);
        }
        __syncthreads();

        // ---- scores: S = (Qr.Kr^T + Qi.Ki^T) * SCALE ----
        {
            float s[4][4] = {{0}};
            #pragma unroll 8
            for (int d = 0; d < HD; d++) {
                const float4 q4r = *(const float4*)&sm.Qr[d][qr0];
                const float4 q4i = *(const float4*)&sm.Qi[d][qr0];
                const float4 k4r = *(const float4*)&sm.Kr[d][kc0];
                const float4 k4i = *(const float4*)&sm.Ki[d][kc0];
                const float qrv[4] = {q4r.x, q4r.y, q4r.z, q4r.w};
                const float qiv[4] = {q4i.x, q4i.y, q4i.z, q4i.w};
                const float krv[4] = {k4r.x, k4r.y, k4r.z, k4r.w};
                const float kiv[4] = {k4i.x, k4i.y, k4i.z, k4i.w};
                #pragma unroll
                for (int i = 0; i < 4; i++)
                    #pragma unroll
                    for (int j = 0; j < 4; j++) {
                        s[i][j] = fmaf(qrv[i], krv[j], s[i][j]);
                        s[i][j] = fmaf(qiv[i], kiv[j], s[i][j]);
                    }
            }
            #pragma unroll
            for (int i = 0; i < 4; i++)
                #pragma unroll
                for (int j = 0; j < 4; j++)
                    sm.S[qr0 + i][kc0 + j] = s[i][j] * ATT_SCALE;
        }
        __syncthreads();

        // ---- online softmax update (4 threads per row) ----
        {
            float mloc = -1e30f;
            #pragma unroll
            for (int c = 0; c < 16; c++) mloc = fmaxf(mloc, sm.S[sq][sc + c]);
            mloc = fmaxf(mloc, __shfl_xor_sync(0xffffffffu, mloc, 1));
            mloc = fmaxf(mloc, __shfl_xor_sync(0xffffffffu, mloc, 2));
            const float m_old = sm.M[sq];
            const float m_new = fmaxf(m_old, mloc);
            float lsum = 0.0f;
            #pragma unroll
            for (int c = 0; c < 16; c++) {
                float pv = __expf(sm.S[sq][sc + c] - m_new);
                sm.S[sq][sc + c] = pv;
                lsum += pv;
            }
            lsum += __shfl_xor_sync(0xffffffffu, lsum, 1);
            lsum += __shfl_xor_sync(0xffffffffu, lsum, 2);
            if ((tid & 3) == 0) {
                float alpha = __expf(m_old - m_new);
                sm.A[sq] = alpha;
                sm.M[sq] = m_new;
                sm.L[sq] = sm.L[sq] * alpha + lsum;
            }
        }
        __syncthreads();

        // ---- output accumulate: o = o*alpha + P @ V ----
        {
            float al[4];
            #pragma unroll
            for (int i = 0; i < 4; i++) al[i] = sm.A[qr0 + i];
            #pragma unroll
            for (int i = 0; i < 4; i++)
                #pragma unroll
                for (int j = 0; j < 4; j++) { oR[i][j] *= al[i]; oI[i][j] *= al[i]; }

            #pragma unroll 8
            for (int k = 0; k < 64; k++) {
                const float p0 = sm.S[qr0 + 0][k];
                const float p1 = sm.S[qr0 + 1][k];
                const float p2 = sm.S[qr0 + 2][k];
                const float p3 = sm.S[qr0 + 3][k];
                const float pv[4] = {p0, p1, p2, p3};
                const float4 v4r = *(const float4*)&sm.Vr[k][dc0];
                const float4 v4i = *(const float4*)&sm.Vi[k][dc0];
                const float vrv[4] = {v4r.x, v4r.y, v4r.z, v4r.w};
                const float viv[4] = {v4i.x, v4i.y, v4i.z, v4i.w};
                #pragma unroll
                for (int i = 0; i < 4; i++)
                    #pragma unroll
                    for (int j = 0; j < 4; j++) {
                        oR[i][j] = fmaf(pv[i], vrv[j], oR[i][j]);
                        oI[i][j] = fmaf(pv[i], viv[j], oI[i][j]);
                    }
            }
        }
        __syncthreads();
    }

    // ---- finalize and write merged-head layout ----
    float linv[4];
    #pragma unroll
    for (int i = 0; i < 4; i++) linv[i] = 1.0f / sm.L[qr0 + i];
    #pragma unroll
    for (int i = 0; i < 4; i++) {
        size_t off = (tok0 + q0g + qr0 + i) * DIMM + col0 + dc0;
        float4 r4 = make_float4(oR[i][0] * linv[i], oR[i][1] * linv[i],
                                oR[i][2] * linv[i], oR[i][3] * linv[i]);
        float4 i4 = make_float4(oI[i][0] * linv[i], oI[i][1] * linv[i],
                                oI[i][2] * linv[i], oI[i][3] * linv[i]);
        *(float4*)(Or + off) = r4;
        *(float4*)(Oi + off) = i4;
    }
}

// ---------------------------------------------------------------------------
extern "C" void kernel_launch(void* const* d_in, const int* in_sizes, int n_in,
                              void* d_out, int out_size)
{
    const float* zr   = (const float*)d_in[0];
    const float* zi   = (const float*)d_in[1];
    const float* wq_r = (const float*)d_in[2];
    const float* wq_i = (const float*)d_in[3];
    const float* wk_r = (const float*)d_in[4];
    const float* wk_i = (const float*)d_in[5];
    const float* wv_r = (const float*)d_in[6];
    const float* wv_i = (const float*)d_in[7];
    const float* wo_r = (const float*)d_in[8];
    const float* wo_i = (const float*)d_in[9];

    float* scratch = nullptr;
    cudaGetSymbolAddress((void**)&scratch, g_scratch);
    float* qr = scratch + 0ull * NTD;
    float* qi = scratch + 1ull * NTD;
    float* kr = scratch + 2ull * NTD;
    float* ki = scratch + 3ull * NTD;
    float* vr = scratch + 4ull * NTD;
    float* vi = scratch + 5ull * NTD;
    float* ar = scratch + 6ull * NTD;
    float* ai = scratch + 7ull * NTD;

    float* yr = (float*)d_out;
    float* yi = (float*)d_out + NTD;

    dim3 gemm_grid(DIMM / 64, NTOK / 64);   // (16, 64)
    clinear_kernel<<<gemm_grid, 256>>>(zr, zi, wq_r, wq_i, qr, qi);
    clinear_kernel<<<gemm_grid, 256>>>(zr, zi, wk_r, wk_i, kr, ki);
    clinear_kernel<<<gemm_grid, 256>>>(zr, zi, wv_r, wv_i, vr, vi);

    static const int kFlashSmem = (int)sizeof(FlashSmem);
    cudaFuncSetAttribute(flash_kernel, cudaFuncAttributeMaxDynamicSharedMemorySize,
                         kFlashSmem);
    dim3 flash_grid(SEQ / 64, BATCH * NH);  // (32, 32)
    flash_kernel<<<flash_grid, 256, kFlashSmem>>>(qr, qi, kr, ki, vr, vi, ar, ai);

    clinear_kernel<<<gemm_grid, 256>>>(ar, ai, wo_r, wo_i, yr, yi);
}

// round 4
// speedup vs baseline: 1.9385x; 1.9385x over previous
#include <cuda_runtime.h>
#include <cuda_bf16.h>
#include <math.h>
#include <stdint.h>

// ---------------------------------------------------------------------------
// HermitianAttention (B=2,S=2048,D=1024,H=16,hd=64) — bf16x3 split tensor-core.
//   [Yr|Yi] = [Xr;Xi]K-stacked @ [[Wr,Wi],[-Wi,Wr]] ; flash attn with d=128.
//   Every operand split hi/lo bf16; C += Ah*Bh + Ah*Bl + Al*Bh (fp32 acc).
// R3 fix: flash K smem pair-dim was [36], must be [68] (64 pairs + pad).
// ---------------------------------------------------------------------------

#define BATCH 2
#define SEQ   2048
#define DIMM  1024
#define NH    16
#define HD    64
#define NTOK  (BATCH * SEQ)
#define NTD   (NTOK * DIMM)
#define ATT_SCALE 0.125f

__device__ float g_scratch[8u * NTD];   // q(2) k(2) v(2) ar ai

__device__ __forceinline__ void cvt2(float x0, float x1, uint32_t& h, uint32_t& l) {
    __nv_bfloat16 h0 = __float2bfloat16_rn(x0);
    __nv_bfloat16 h1 = __float2bfloat16_rn(x1);
    float r0 = x0 - __bfloat162float(h0);
    float r1 = x1 - __bfloat162float(h1);
    __nv_bfloat16 l0 = __float2bfloat16_rn(r0);
    __nv_bfloat16 l1 = __float2bfloat16_rn(r1);
    h = ((uint32_t)__bfloat16_as_ushort(h1) << 16) | __bfloat16_as_ushort(h0);
    l = ((uint32_t)__bfloat16_as_ushort(l1) << 16) | __bfloat16_as_ushort(l0);
}

__device__ __forceinline__ void mma16(float c[4], const uint32_t a[4], const uint32_t b[2]) {
    asm volatile(
        "mma.sync.aligned.m16n8k16.row.col.f32.bf16.bf16.f32 "
        "{%0,%1,%2,%3}, {%4,%5,%6,%7}, {%8,%9}, {%0,%1,%2,%3};\n"
        : "+f"(c[0]), "+f"(c[1]), "+f"(c[2]), "+f"(c[3])
        : "r"(a[0]), "r"(a[1]), "r"(a[2]), "r"(a[3]), "r"(b[0]), "r"(b[1]));
}

// ---------------------------------------------------------------------------
// Stacked complex GEMM: M=4096, K=2048, N=2048. BM=BN=128, BK=32.
// 128 threads, 4 warps (2x2), warp tile 64x64.
// ---------------------------------------------------------------------------
__global__ void __launch_bounds__(128, 2)
cgemm_bf16x3(const float* __restrict__ Xr, const float* __restrict__ Xi,
             const float* __restrict__ Wr, const float* __restrict__ Wi,
             float* __restrict__ Y0, float* __restrict__ Y1, int ldY)
{
    __shared__ uint32_t sAh[128][20], sAl[128][20];   // [m][kpair], pad 20
    __shared__ uint32_t sBh[16][136], sBl[16][136];   // [kpair][n], pad 136

    const int tid = threadIdx.x;
    const int w = tid >> 5, lane = tid & 31;
    const int grp = lane >> 2, tk = lane & 3;
    const int warpM = (w >> 1) * 64;
    const int warpN = (w & 1) * 64;
    const int bm = blockIdx.y * 128;
    const int bn = blockIdx.x * 128;
    const bool is_ni = (bn >= DIMM);
    const int bn_m = bn & (DIMM - 1);

    float acc[4][8][4];
    #pragma unroll
    for (int mi = 0; mi < 4; mi++)
        #pragma unroll
        for (int ni = 0; ni < 8; ni++)
            #pragma unroll
            for (int v = 0; v < 4; v++) acc[mi][ni][v] = 0.0f;

    for (int k0 = 0; k0 < 2 * DIMM; k0 += 32) {
        // ---- A tile 128x32 -> hi/lo pairs along k ----
        {
            const float* Asrc; int acol;
            if (k0 < DIMM) { Asrc = Xr; acol = k0; } else { Asrc = Xi; acol = k0 - DIMM; }
            #pragma unroll
            for (int it = 0; it < 8; it++) {
                int task = tid + it * 128;          // 0..1023
                int r = task >> 3, j = task & 7;
                float4 v4 = *(const float4*)(Asrc + (size_t)(bm + r) * DIMM + acol + j * 4);
                uint32_t h0, l0, h1, l1;
                cvt2(v4.x, v4.y, h0, l0);
                cvt2(v4.z, v4.w, h1, l1);
                sAh[r][j * 2] = h0; sAh[r][j * 2 + 1] = h1;
                sAl[r][j * 2] = l0; sAl[r][j * 2 + 1] = l1;
            }
        }
        // ---- B tile 32x128 synthesized, hi/lo pairs along k ----
        {
            const float* Bsrc; int brow; float bs;
            if (k0 < DIMM) { brow = k0; bs = 1.0f; Bsrc = is_ni ? Wi : Wr; }
            else {
                brow = k0 - DIMM;
                if (is_ni) { Bsrc = Wr; bs = 1.0f; } else { Bsrc = Wi; bs = -1.0f; }
            }
            #pragma unroll
            for (int it = 0; it < 4; it++) {
                int task = tid + it * 128;          // 0..511
                int p = task >> 5, j = task & 31;   // pair row (0..15), col/4
                const float* g0 = Bsrc + (size_t)(brow + 2 * p) * DIMM + bn_m + j * 4;
                const float* g1 = g0 + DIMM;
                float4 a4 = *(const float4*)g0;
                float4 b4 = *(const float4*)g1;
                uint32_t h, l;
                cvt2(a4.x * bs, b4.x * bs, h, l); sBh[p][j*4+0] = h; sBl[p][j*4+0] = l;
                cvt2(a4.y * bs, b4.y * bs, h, l); sBh[p][j*4+1] = h; sBl[p][j*4+1] = l;
                cvt2(a4.z * bs, b4.z * bs, h, l); sBh[p][j*4+2] = h; sBl[p][j*4+2] = l;
                cvt2(a4.w * bs, b4.w * bs, h, l); sBh[p][j*4+3] = h; sBl[p][j*4+3] = l;
            }
        }
        __syncthreads();

        #pragma unroll
        for (int kk = 0; kk < 2; kk++) {            // two k16 chunks
            uint32_t afh[4][4], afl[4][4];
            #pragma unroll
            for (int mi = 0; mi < 4; mi++) {
                int m0 = warpM + mi * 16;
                afh[mi][0] = sAh[m0 + grp    ][kk * 8 + tk    ];
                afh[mi][1] = sAh[m0 + grp + 8][kk * 8 + tk    ];
                afh[mi][2] = sAh[m0 + grp    ][kk * 8 + tk + 4];
                afh[mi][3] = sAh[m0 + grp + 8][kk * 8 + tk + 4];
                afl[mi][0] = sAl[m0 + grp    ][kk * 8 + tk    ];
                afl[mi][1] = sAl[m0 + grp + 8][kk * 8 + tk    ];
                afl[mi][2] = sAl[m0 + grp    ][kk * 8 + tk + 4];
                afl[mi][3] = sAl[m0 + grp + 8][kk * 8 + tk + 4];
            }
            #pragma unroll
            for (int ni = 0; ni < 8; ni++) {
                int n0 = warpN + ni * 8;
                uint32_t bfh[2], bfl[2];
                bfh[0] = sBh[kk * 8 + tk    ][n0 + grp];
                bfh[1] = sBh[kk * 8 + tk + 4][n0 + grp];
                bfl[0] = sBl[kk * 8 + tk    ][n0 + grp];
                bfl[1] = sBl[kk * 8 + tk + 4][n0 + grp];
                #pragma unroll
                for (int mi = 0; mi < 4; mi++) {
                    mma16(acc[mi][ni], afh[mi], bfh);
                    mma16(acc[mi][ni], afh[mi], bfl);
                    mma16(acc[mi][ni], afl[mi], bfh);
                }
            }
        }
        __syncthreads();
    }

    #pragma unroll
    for (int mi = 0; mi < 4; mi++) {
        int m = bm + warpM + mi * 16 + grp;
        #pragma unroll
        for (int ni = 0; ni < 8; ni++) {
            int n = bn + warpN + ni * 8 + tk * 2;
            float* base; int nn;
            if (n < DIMM) { base = Y0; nn = n; } else { base = Y1; nn = n - DIMM; }
            *(float2*)(base + (size_t)m * ldY + nn) =
                make_float2(acc[mi][ni][0], acc[mi][ni][1]);
            *(float2*)(base + (size_t)(m + 8) * ldY + nn) =
                make_float2(acc[mi][ni][2], acc[mi][ni][3]);
        }
    }
}

// ---------------------------------------------------------------------------
// Flash attention bf16x3. CTA: 128 q rows of one (b,h); key tiles of 64.
// 8 warps: scores warp tile 32x32 (4x2), PV warp tile 32x64.
// ---------------------------------------------------------------------------
struct FSmem {
    uint32_t Qh[128][68], Ql[128][68];   // [q][d_pair]   64 pairs + pad
    uint32_t Kh[64][68],  Kl[64][68];    // [key][d_pair] 64 pairs + pad (R3 fix)
    uint32_t Vh[32][136], Vl[32][136];   // [key_pair][d] 128 cols + pad
    uint32_t Ph[128][36], Pl[128][36];   // [q][key_pair] 32 pairs + pad
    float S[128][68];                    // fp32 scores 64 + pad
    float M[128], L[128], Al[128];
};

__global__ void __launch_bounds__(256, 1)
flash_bf16x3(const float* __restrict__ Qg, const float* __restrict__ Kg,
             const float* __restrict__ Vg, float* __restrict__ Ar,
             float* __restrict__ Ai)
{
    extern __shared__ char raw[];
    FSmem& s = *reinterpret_cast<FSmem*>(raw);

    const int tid = threadIdx.x;
    const int w = tid >> 5, lane = tid & 31;
    const int grp = lane >> 2, tk = lane & 3;
    const int warpM = w >> 1;   // 0..3
    const int warpN = w & 1;    // 0..1
    const int bh = blockIdx.y;
    const int b = bh >> 4, h = bh & 15;
    const int qt = blockIdx.x;
    const size_t tokb = (size_t)b * SEQ;
    const int colr = h * HD;
    const int coli = DIMM + h * HD;

    // ---- Q tile 128x128 -> hi/lo pairs ----
    #pragma unroll
    for (int it = 0; it < 16; it++) {
        int task = tid + it * 256;           // 0..4095
        int r = task >> 5, j = task & 31;
        int c = j * 4;
        int off = (c < HD) ? (colr + c) : (coli + c - HD);
        float4 v4 = *(const float4*)(Qg + (tokb + qt * 128 + r) * (size_t)(2 * DIMM) + off);
        uint32_t h0, l0, h1, l1;
        cvt2(v4.x, v4.y, h0, l0);
        cvt2(v4.z, v4.w, h1, l1);
        s.Qh[r][j * 2] = h0; s.Qh[r][j * 2 + 1] = h1;
        s.Ql[r][j * 2] = l0; s.Ql[r][j * 2 + 1] = l1;
    }
    if (tid < 128) { s.M[tid] = -1e30f; s.L[tid] = 0.0f; }

    float o[2][8][4];
    #pragma unroll
    for (int mi = 0; mi < 2; mi++)
        #pragma unroll
        for (int ni = 0; ni < 8; ni++)
            #pragma unroll
            for (int v = 0; v < 4; v++) o[mi][ni][v] = 0.0f;

    __syncthreads();

    for (int kt = 0; kt < SEQ / 64; kt++) {
        // ---- K tile 64x128: [key][d_pair] ----
        #pragma unroll
        for (int it = 0; it < 8; it++) {
            int task = tid + it * 256;        // 0..2047
            int r = task >> 5, j = task & 31;
            int c = j * 4;
            int off = (c < HD) ? (colr + c) : (coli + c - HD);
            size_t g = (tokb + kt * 64 + r) * (size_t)(2 * DIMM) + off;
            float4 kv = *(const float4*)(Kg + g);
            uint32_t h0, l0, h1, l1;
            cvt2(kv.x, kv.y, h0, l0);
            cvt2(kv.z, kv.w, h1, l1);
            s.Kh[r][j * 2] = h0; s.Kh[r][j * 2 + 1] = h1;
            s.Kl[r][j * 2] = l0; s.Kl[r][j * 2 + 1] = l1;
        }
        // ---- V tile 64x128: [key_pair][d], pack two key rows ----
        #pragma unroll
        for (int it = 0; it < 4; it++) {
            int task = tid + it * 256;        // 0..1023
            int p = task >> 5, j = task & 31; // key pair, col/4
            int c = j * 4;
            int off = (c < HD) ? (colr + c) : (coli + c - HD);
            size_t g0 = (tokb + kt * 64 + 2 * p) * (size_t)(2 * DIMM) + off;
            float4 a4 = *(const float4*)(Vg + g0);
            float4 b4 = *(const float4*)(Vg + g0 + 2 * DIMM);
            uint32_t hh, ll;
            cvt2(a4.x, b4.x, hh, ll); s.Vh[p][c + 0] = hh; s.Vl[p][c + 0] = ll;
            cvt2(a4.y, b4.y, hh, ll); s.Vh[p][c + 1] = hh; s.Vl[p][c + 1] = ll;
            cvt2(a4.z, b4.z, hh, ll); s.Vh[p][c + 2] = hh; s.Vl[p][c + 2] = ll;
            cvt2(a4.w, b4.w, hh, ll); s.Vh[p][c + 3] = hh; s.Vl[p][c + 3] = ll;
        }
        __syncthreads();

        // ---- scores 128x64 (warp 32x32) ----
        {
            float sc[2][4][4];
            #pragma unroll
            for (int mi = 0; mi < 2; mi++)
                #pragma unroll
                for (int ni = 0; ni < 4; ni++)
                    #pragma unroll
                    for (int v = 0; v < 4; v++) sc[mi][ni][v] = 0.0f;

            #pragma unroll
            for (int kk = 0; kk < 8; kk++) {       // d = 128 = 8 x k16
                uint32_t afh[2][4], afl[2][4];
                #pragma unroll
                for (int mi = 0; mi < 2; mi++) {
                    int m0 = warpM * 32 + mi * 16;
                    afh[mi][0] = s.Qh[m0 + grp    ][kk * 8 + tk    ];
                    afh[mi][1] = s.Qh[m0 + grp + 8][kk * 8 + tk    ];
                    afh[mi][2] = s.Qh[m0 + grp    ][kk * 8 + tk + 4];
                    afh[mi][3] = s.Qh[m0 + grp + 8][kk * 8 + tk + 4];
                    afl[mi][0] = s.Ql[m0 + grp    ][kk * 8 + tk    ];
                    afl[mi][1] = s.Ql[m0 + grp + 8][kk * 8 + tk    ];
                    afl[mi][2] = s.Ql[m0 + grp    ][kk * 8 + tk + 4];
                    afl[mi][3] = s.Ql[m0 + grp + 8][kk * 8 + tk + 4];
                }
                #pragma unroll
                for (int ni = 0; ni < 4; ni++) {
                    int n0 = warpN * 32 + ni * 8;
                    uint32_t bfh[2], bfl[2];
                    bfh[0] = s.Kh[n0 + grp][kk * 8 + tk    ];
                    bfh[1] = s.Kh[n0 + grp][kk * 8 + tk + 4];
                    bfl[0] = s.Kl[n0 + grp][kk * 8 + tk    ];
                    bfl[1] = s.Kl[n0 + grp][kk * 8 + tk + 4];
                    #pragma unroll
                    for (int mi = 0; mi < 2; mi++) {
                        mma16(sc[mi][ni], afh[mi], bfh);
                        mma16(sc[mi][ni], afh[mi], bfl);
                        mma16(sc[mi][ni], afl[mi], bfh);
                    }
                }
            }
            #pragma unroll
            for (int mi = 0; mi < 2; mi++) {
                int rr = warpM * 32 + mi * 16 + grp;
                #pragma unroll
                for (int ni = 0; ni < 4; ni++) {
                    int cc = warpN * 32 + ni * 8 + tk * 2;
                    *(float2*)&s.S[rr][cc] =
                        make_float2(sc[mi][ni][0] * ATT_SCALE, sc[mi][ni][1] * ATT_SCALE);
                    *(float2*)&s.S[rr + 8][cc] =
                        make_float2(sc[mi][ni][2] * ATT_SCALE, sc[mi][ni][3] * ATT_SCALE);
                }
            }
        }
        __syncthreads();

        // ---- online softmax; write P hi/lo pairs ----
        {
            int rr = tid >> 1, c0 = (tid & 1) * 32;
            float mx = -1e30f;
            #pragma unroll
            for (int c = 0; c < 32; c++) mx = fmaxf(mx, s.S[rr][c0 + c]);
            mx = fmaxf(mx, __shfl_xor_sync(0xffffffffu, mx, 1));
            float mold = s.M[rr];
            float mnew = fmaxf(mold, mx);
            float ls = 0.0f;
            #pragma unroll
            for (int jp = 0; jp < 16; jp++) {
                float e0 = __expf(s.S[rr][c0 + 2 * jp    ] - mnew);
                float e1 = __expf(s.S[rr][c0 + 2 * jp + 1] - mnew);
                ls += e0 + e1;
                uint32_t hh, ll;
                cvt2(e0, e1, hh, ll);
                s.Ph[rr][c0 / 2 + jp] = hh;
                s.Pl[rr][c0 / 2 + jp] = ll;
            }
            ls += __shfl_xor_sync(0xffffffffu, ls, 1);
            if ((tid & 1) == 0) {
                float al = __expf(mold - mnew);
                s.M[rr] = mnew;
                s.Al[rr] = al;
                s.L[rr] = s.L[rr] * al + ls;
            }
        }
        __syncthreads();

        // ---- rescale + PV 128x128 (warp 32x64) ----
        {
            #pragma unroll
            for (int mi = 0; mi < 2; mi++) {
                int r0 = warpM * 32 + mi * 16 + grp;
                float a0 = s.Al[r0], a1 = s.Al[r0 + 8];
                #pragma unroll
                for (int ni = 0; ni < 8; ni++) {
                    o[mi][ni][0] *= a0; o[mi][ni][1] *= a0;
                    o[mi][ni][2] *= a1; o[mi][ni][3] *= a1;
                }
            }
            #pragma unroll
            for (int kk = 0; kk < 4; kk++) {       // key = 64 = 4 x k16
                uint32_t afh[2][4], afl[2][4];
                #pragma unroll
                for (int mi = 0; mi < 2; mi++) {
                    int m0 = warpM * 32 + mi * 16;
                    afh[mi][0] = s.Ph[m0 + grp    ][kk * 8 + tk    ];
                    afh[mi][1] = s.Ph[m0 + grp + 8][kk * 8 + tk    ];
                    afh[mi][2] = s.Ph[m0 + grp    ][kk * 8 + tk + 4];
                    afh[mi][3] = s.Ph[m0 + grp + 8][kk * 8 + tk + 4];
                    afl[mi][0] = s.Pl[m0 + grp    ][kk * 8 + tk    ];
                    afl[mi][1] = s.Pl[m0 + grp + 8][kk * 8 + tk    ];
                    afl[mi][2] = s.Pl[m0 + grp    ][kk * 8 + tk + 4];
                    afl[mi][3] = s.Pl[m0 + grp + 8][kk * 8 + tk + 4];
                }
                #pragma unroll
                for (int ni = 0; ni < 8; ni++) {
                    int n0 = warpN * 64 + ni * 8;
                    uint32_t bfh[2], bfl[2];
                    bfh[0] = s.Vh[kk * 8 + tk    ][n0 + grp];
                    bfh[1] = s.Vh[kk * 8 + tk + 4][n0 + grp];
                    bfl[0] = s.Vl[kk * 8 + tk    ][n0 + grp];
                    bfl[1] = s.Vl[kk * 8 + tk + 4][n0 + grp];
                    #pragma unroll
                    for (int mi = 0; mi < 2; mi++) {
                        mma16(o[mi][ni], afh[mi], bfh);
                        mma16(o[mi][ni], afh[mi], bfl);
                        mma16(o[mi][ni], afl[mi], bfh);
                    }
                }
            }
        }
        __syncthreads();
    }

    // ---- finalize ----
    #pragma unroll
    for (int mi = 0; mi < 2; mi++) {
        int r0 = warpM * 32 + mi * 16 + grp;
        float l0 = 1.0f / s.L[r0];
        float l1 = 1.0f / s.L[r0 + 8];
        int tok = b * SEQ + qt * 128;
        #pragma unroll
        for (int ni = 0; ni < 8; ni++) {
            int c = warpN * 64 + ni * 8 + tk * 2;
            float* dst; int cc;
            if (c < HD) { dst = Ar; cc = c; } else { dst = Ai; cc = c - HD; }
            *(float2*)(dst + (size_t)(tok + r0) * DIMM + colr + cc) =
                make_float2(o[mi][ni][0] * l0, o[mi][ni][1] * l0);
            *(float2*)(dst + (size_t)(tok + r0 + 8) * DIMM + colr + cc) =
                make_float2(o[mi][ni][2] * l1, o[mi][ni][3] * l1);
        }
    }
}

// ---------------------------------------------------------------------------
extern "C" void kernel_launch(void* const* d_in, const int* in_sizes, int n_in,
                              void* d_out, int out_size)
{
    const float* zr   = (const float*)d_in[0];
    const float* zi   = (const float*)d_in[1];
    const float* wq_r = (const float*)d_in[2];
    const float* wq_i = (const float*)d_in[3];
    const float* wk_r = (const float*)d_in[4];
    const float* wk_i = (const float*)d_in[5];
    const float* wv_r = (const float*)d_in[6];
    const float* wv_i = (const float*)d_in[7];
    const float* wo_r = (const float*)d_in[8];
    const float* wo_i = (const float*)d_in[9];

    float* scratch = nullptr;
    cudaGetSymbolAddress((void**)&scratch, g_scratch);
    float* q  = scratch + 0ull * NTD;   // [4096][2048] = [Qr|Qi]
    float* k  = scratch + 2ull * NTD;
    float* v  = scratch + 4ull * NTD;
    float* ar = scratch + 6ull * NTD;
    float* ai = scratch + 7ull * NTD;

    float* yr = (float*)d_out;
    float* yi = (float*)d_out + NTD;

    dim3 ggrid(2 * DIMM / 128, NTOK / 128);   // (16, 32)
    cgemm_bf16x3<<<ggrid, 128>>>(zr, zi, wq_r, wq_i, q, q + DIMM, 2 * DIMM);
    cgemm_bf16x3<<<ggrid, 128>>>(zr, zi, wk_r, wk_i, k, k + DIMM, 2 * DIMM);
    cgemm_bf16x3<<<ggrid, 128>>>(zr, zi, wv_r, wv_i, v, v + DIMM, 2 * DIMM);

    static const int kSmem = (int)sizeof(FSmem);
    cudaFuncSetAttribute(flash_bf16x3, cudaFuncAttributeMaxDynamicSharedMemorySize, kSmem);
    dim3 fgrid(SEQ / 128, BATCH * NH);        // (16, 32)
    flash_bf16x3<<<fgrid, 256, kSmem>>>(q, k, v, ar, ai);

    cgemm_bf16x3<<<ggrid, 128>>>(ar, ai, wo_r, wo_i, yr, yi, DIMM);
}

// round 5
// speedup vs baseline: 2.1637x; 1.1162x over previous
#include <cuda_runtime.h>
#include <cuda_bf16.h>
#include <math.h>
#include <stdint.h>

// ---------------------------------------------------------------------------
// HermitianAttention (B=2,S=2048,D=1024,H=16,hd=64) — bf16x3, pre-packed.
//  R5: hi/lo split hoisted into one-time pack kernels; GEMM = pure bf16
//  cp.async double-buffered; flash fills = raw copies / PRMT repack.
// ---------------------------------------------------------------------------

#define BATCH 2
#define SEQ   2048
#define DIMM  1024
#define NH    16
#define HD    64
#define NTOK  (BATCH * SEQ)
#define NTD   (NTOK * DIMM)
#define KP    1024              // k-pairs of the stacked K=2048
#define ATT_SCALE 0.125f

// u32 scratch: Az(8M) B4(16M) QKV(24M) Ao(8M) = 56M u32 = 224MB
#define MEGA (1024u * 1024u)
__device__ uint32_t g_scratch[56u * MEGA];

__device__ __forceinline__ void cvt2(float x0, float x1, uint32_t& h, uint32_t& l) {
    __nv_bfloat16 h0 = __float2bfloat16_rn(x0);
    __nv_bfloat16 h1 = __float2bfloat16_rn(x1);
    float r0 = x0 - __bfloat162float(h0);
    float r1 = x1 - __bfloat162float(h1);
    __nv_bfloat16 l0 = __float2bfloat16_rn(r0);
    __nv_bfloat16 l1 = __float2bfloat16_rn(r1);
    h = ((uint32_t)__bfloat16_as_ushort(h1) << 16) | __bfloat16_as_ushort(h0);
    l = ((uint32_t)__bfloat16_as_ushort(l1) << 16) | __bfloat16_as_ushort(l0);
}

__device__ __forceinline__ void mma16(float c[4], const uint32_t a[4], const uint32_t b[2]) {
    asm volatile(
        "mma.sync.aligned.m16n8k16.row.col.f32.bf16.bf16.f32 "
        "{%0,%1,%2,%3}, {%4,%5,%6,%7}, {%8,%9}, {%0,%1,%2,%3};\n"
        : "+f"(c[0]), "+f"(c[1]), "+f"(c[2]), "+f"(c[3])
        : "r"(a[0]), "r"(a[1]), "r"(a[2]), "r"(a[3]), "r"(b[0]), "r"(b[1]));
}

__device__ __forceinline__ void cpa16(void* dst, const void* src) {
    uint32_t d = (uint32_t)__cvta_generic_to_shared(dst);
    asm volatile("cp.async.cg.shared.global [%0], [%1], 16;\n" :: "r"(d), "l"(src));
}
#define CP_COMMIT() asm volatile("cp.async.commit_group;\n" ::: "memory")

// ---------------------------------------------------------------------------
// Pack kernels (run once per call, memory-bound).
// ---------------------------------------------------------------------------
__global__ void pack_x(const float* __restrict__ zr, const float* __restrict__ zi,
                       uint32_t* __restrict__ Ah, uint32_t* __restrict__ Al)
{
    int p = blockIdx.x * blockDim.x + threadIdx.x;   // 0..4096*1024-1
    int m = p >> 10, j = p & 1023;
    const float* src = (j < 512) ? zr : zi;
    int c = (j < 512) ? (j * 2) : ((j - 512) * 2);
    float2 v = *(const float2*)(src + (size_t)m * DIMM + c);
    uint32_t h, l; cvt2(v.x, v.y, h, l);
    Ah[p] = h; Al[p] = l;
}

__global__ void pack_w(const float* __restrict__ Wr, const float* __restrict__ Wi,
                       uint32_t* __restrict__ Bh, uint32_t* __restrict__ Bl)
{
    // out [1024 kpairs][2048 n] of stacked [[Wr,Wi],[-Wi,Wr]]
    int idx = blockIdx.x * blockDim.x + threadIdx.x;   // 0..1024*2048-1
    int p = idx >> 11, n = idx & 2047;
    int k0 = 2 * p;
    float a, b;
    if (p < 512) {
        if (n < 1024) {
            a = Wr[(size_t)k0 * DIMM + n];       b = Wr[(size_t)(k0 + 1) * DIMM + n];
        } else {
            int nn = n - 1024;
            a = Wi[(size_t)k0 * DIMM + nn];      b = Wi[(size_t)(k0 + 1) * DIMM + nn];
        }
    } else {
        int kk = k0 - 1024;
        if (n < 1024) {
            a = -Wi[(size_t)kk * DIMM + n];      b = -Wi[(size_t)(kk + 1) * DIMM + n];
        } else {
            int nn = n - 1024;
            a = Wr[(size_t)kk * DIMM + nn];      b = Wr[(size_t)(kk + 1) * DIMM + nn];
        }
    }
    uint32_t h, l; cvt2(a, b, h, l);
    Bh[idx] = h; Bl[idx] = l;
}

// ---------------------------------------------------------------------------
// bf16x3 GEMM on pre-packed operands. M=4096, Kpairs=1024, N=2048.
// BM=BN=128, 16 kpairs per stage, 2-stage cp.async pipeline.
// 128 threads, 4 warps (2x2), warp tile 64x64.
// ---------------------------------------------------------------------------
__global__ void __launch_bounds__(128, 2)
gemm_bf16x3(const uint32_t* __restrict__ Ah, const uint32_t* __restrict__ Al,
            const uint32_t* __restrict__ Bh, const uint32_t* __restrict__ Bl,
            uint32_t* __restrict__ Yh, uint32_t* __restrict__ Yl,   // packed out
            float* __restrict__ Y0, float* __restrict__ Y1,         // f32 out
            int pack_out)
{
    __shared__ uint32_t sAh[2][128][20], sAl[2][128][20];
    __shared__ uint32_t sBh[2][16][136], sBl[2][16][136];

    const int tid = threadIdx.x;
    const int w = tid >> 5, lane = tid & 31;
    const int grp = lane >> 2, tk = lane & 3;
    const int warpM = (w >> 1) * 64;
    const int warpN = (w & 1) * 64;
    const int bm = blockIdx.y * 128;
    const int bn = blockIdx.x * 128;

    float acc[4][8][4];
    #pragma unroll
    for (int mi = 0; mi < 4; mi++)
        #pragma unroll
        for (int ni = 0; ni < 8; ni++)
            #pragma unroll
            for (int v = 0; v < 4; v++) acc[mi][ni][v] = 0.0f;

    auto fill = [&](int s, int kp) {
        #pragma unroll
        for (int it = 0; it < 8; it++) {
            int task = tid + it * 128;          // 0..1023
            int t2 = task & 511;
            int r = t2 >> 2, c = (t2 & 3) * 4;
            const uint32_t* src = (task < 512 ? Ah : Al) + (size_t)(bm + r) * KP + kp + c;
            if (task < 512) cpa16(&sAh[s][r][c], src);
            else            cpa16(&sAl[s][r][c], src);
        }
        #pragma unroll
        for (int it = 0; it < 8; it++) {
            int task = tid + it * 128;
            int t2 = task & 511;
            int p = t2 >> 5, c = (t2 & 31) * 4;
            const uint32_t* src = (task < 512 ? Bh : Bl) + (size_t)(kp + p) * 2048 + bn + c;
            if (task < 512) cpa16(&sBh[s][p][c], src);
            else            cpa16(&sBl[s][p][c], src);
        }
    };

    fill(0, 0);
    CP_COMMIT();

    for (int st = 0; st < 64; st++) {
        int cur = st & 1;
        if (st + 1 < 64) {
            fill(cur ^ 1, (st + 1) * 16);
            CP_COMMIT();
            asm volatile("cp.async.wait_group 1;\n" ::: "memory");
        } else {
            asm volatile("cp.async.wait_group 0;\n" ::: "memory");
        }
        __syncthreads();

        #pragma unroll
        for (int kk = 0; kk < 2; kk++) {
            uint32_t afh[4][4], afl[4][4];
            #pragma unroll
            for (int mi = 0; mi < 4; mi++) {
                int m0 = warpM + mi * 16;
                afh[mi][0] = sAh[cur][m0 + grp    ][kk * 8 + tk    ];
                afh[mi][1] = sAh[cur][m0 + grp + 8][kk * 8 + tk    ];
                afh[mi][2] = sAh[cur][m0 + grp    ][kk * 8 + tk + 4];
                afh[mi][3] = sAh[cur][m0 + grp + 8][kk * 8 + tk + 4];
                afl[mi][0] = sAl[cur][m0 + grp    ][kk * 8 + tk    ];
                afl[mi][1] = sAl[cur][m0 + grp + 8][kk * 8 + tk    ];
                afl[mi][2] = sAl[cur][m0 + grp    ][kk * 8 + tk + 4];
                afl[mi][3] = sAl[cur][m0 + grp + 8][kk * 8 + tk + 4];
            }
            #pragma unroll
            for (int ni = 0; ni < 8; ni++) {
                int n0 = warpN + ni * 8;
                uint32_t bfh[2], bfl[2];
                bfh[0] = sBh[cur][kk * 8 + tk    ][n0 + grp];
                bfh[1] = sBh[cur][kk * 8 + tk + 4][n0 + grp];
                bfl[0] = sBl[cur][kk * 8 + tk    ][n0 + grp];
                bfl[1] = sBl[cur][kk * 8 + tk + 4][n0 + grp];
                #pragma unroll
                for (int mi = 0; mi < 4; mi++) {
                    mma16(acc[mi][ni], afh[mi], bfh);
                    mma16(acc[mi][ni], afh[mi], bfl);
                    mma16(acc[mi][ni], afl[mi], bfh);
                }
            }
        }
        __syncthreads();
    }

    // ---- epilogue ----
    if (pack_out) {
        #pragma unroll
        for (int mi = 0; mi < 4; mi++) {
            int m = bm + warpM + mi * 16 + grp;
            #pragma unroll
            for (int ni = 0; ni < 8; ni++) {
                int n = bn + warpN + ni * 8 + tk * 2;
                uint32_t h, l;
                cvt2(acc[mi][ni][0], acc[mi][ni][1], h, l);
                Yh[(size_t)m * KP + (n >> 1)] = h;
                Yl[(size_t)m * KP + (n >> 1)] = l;
                cvt2(acc[mi][ni][2], acc[mi][ni][3], h, l);
                Yh[(size_t)(m + 8) * KP + (n >> 1)] = h;
                Yl[(size_t)(m + 8) * KP + (n >> 1)] = l;
            }
        }
    } else {
        #pragma unroll
        for (int mi = 0; mi < 4; mi++) {
            int m = bm + warpM + mi * 16 + grp;
            #pragma unroll
            for (int ni = 0; ni < 8; ni++) {
                int n = bn + warpN + ni * 8 + tk * 2;
                float* base; int nn;
                if (n < DIMM) { base = Y0; nn = n; } else { base = Y1; nn = n - DIMM; }
                *(float2*)(base + (size_t)m * DIMM + nn) =
                    make_float2(acc[mi][ni][0], acc[mi][ni][1]);
                *(float2*)(base + (size_t)(m + 8) * DIMM + nn) =
                    make_float2(acc[mi][ni][2], acc[mi][ni][3]);
            }
        }
    }
}

// ---------------------------------------------------------------------------
// Flash attention bf16x3 on pre-packed q/k/v. Fills are raw copies (Q,K) and
// PRMT repack (V). P converted inline. Output packed hi/lo for the O GEMM.
// ---------------------------------------------------------------------------
struct FSmem {
    uint32_t Qh[128][68], Ql[128][68];   // [q][d_pair]
    uint32_t Kh[64][68],  Kl[64][68];    // [key][d_pair]
    uint32_t Vh[32][136], Vl[32][136];   // [key_pair][d]
    uint32_t Ph[128][36], Pl[128][36];   // [q][key_pair]
    float S[128][68];
    float M[128], L[128], Al[128];
};

__global__ void __launch_bounds__(256, 1)
flash_bf16x3(const uint32_t* __restrict__ Qph, const uint32_t* __restrict__ Qpl,
             const uint32_t* __restrict__ Kph, const uint32_t* __restrict__ Kpl,
             const uint32_t* __restrict__ Vph, const uint32_t* __restrict__ Vpl,
             uint32_t* __restrict__ Aoh, uint32_t* __restrict__ Aol)
{
    extern __shared__ char raw[];
    FSmem& s = *reinterpret_cast<FSmem*>(raw);

    const int tid = threadIdx.x;
    const int w = tid >> 5, lane = tid & 31;
    const int grp = lane >> 2, tk = lane & 3;
    const int warpM = w >> 1;
    const int warpN = w & 1;
    const int bh = blockIdx.y;
    const int b = bh >> 4, h = bh & 15;
    const int qt = blockIdx.x;
    const size_t tokb = (size_t)b * SEQ;
    const int cph = h * 32;              // u32 col base of r-half
    const int colr = h * HD;

    // ---- Q tile: 128 rows x 64 u32 pairs (copy) ----
    #pragma unroll
    for (int it = 0; it < 16; it++) {
        int task = tid + it * 256;            // 0..4095
        int t2 = task & 2047;
        int r = t2 >> 4, cj = t2 & 15;
        int jj = (cj < 8) ? (cph + cj * 4) : (512 + cph + (cj - 8) * 4);
        const uint32_t* src = (task < 2048 ? Qph : Qpl) + (tokb + qt * 128 + r) * KP + jj;
        uint4 v = *(const uint4*)src;
        uint32_t* dst = (task < 2048) ? &s.Qh[r][cj * 4] : &s.Ql[r][cj * 4];
        dst[0] = v.x; dst[1] = v.y; dst[2] = v.z; dst[3] = v.w;
    }
    if (tid < 128) { s.M[tid] = -1e30f; s.L[tid] = 0.0f; }

    float o[2][8][4];
    #pragma unroll
    for (int mi = 0; mi < 2; mi++)
        #pragma unroll
        for (int ni = 0; ni < 8; ni++)
            #pragma unroll
            for (int v = 0; v < 4; v++) o[mi][ni][v] = 0.0f;

    __syncthreads();

    for (int kt = 0; kt < SEQ / 64; kt++) {
        // ---- K tile: 64 x 64 u32 (copy) ----
        #pragma unroll
        for (int it = 0; it < 8; it++) {
            int task = tid + it * 256;        // 0..2047
            int t2 = task & 1023;
            int r = t2 >> 4, cj = t2 & 15;
            int jj = (cj < 8) ? (cph + cj * 4) : (512 + cph + (cj - 8) * 4);
            const uint32_t* src = (task < 1024 ? Kph : Kpl) + (tokb + kt * 64 + r) * KP + jj;
            uint4 v = *(const uint4*)src;
            uint32_t* dst = (task < 1024) ? &s.Kh[r][cj * 4] : &s.Kl[r][cj * 4];
            dst[0] = v.x; dst[1] = v.y; dst[2] = v.z; dst[3] = v.w;
        }
        // ---- V tile: repack col-pairs -> key-pairs via PRMT ----
        #pragma unroll
        for (int it = 0; it < 4; it++) {
            int task = tid + it * 256;        // 0..1023
            int t2 = task & 511;
            int p = t2 >> 4, cj = t2 & 15;
            int jj = (cj < 8) ? (cph + cj * 4) : (512 + cph + (cj - 8) * 4);
            int db = (cj < 8) ? (cj * 8) : (64 + (cj - 8) * 8);
            const uint32_t* base = (task < 512) ? Vph : Vpl;
            const uint32_t* r0 = base + (tokb + kt * 64 + 2 * p) * KP + jj;
            uint4 a4 = *(const uint4*)r0;
            uint4 b4 = *(const uint4*)(r0 + KP);
            uint32_t* dst = (task < 512) ? &s.Vh[p][db] : &s.Vl[p][db];
            dst[0] = __byte_perm(a4.x, b4.x, 0x5410);
            dst[1] = __byte_perm(a4.x, b4.x, 0x7632);
            dst[2] = __byte_perm(a4.y, b4.y, 0x5410);
            dst[3] = __byte_perm(a4.y, b4.y, 0x7632);
            dst[4] = __byte_perm(a4.z, b4.z, 0x5410);
            dst[5] = __byte_perm(a4.z, b4.z, 0x7632);
            dst[6] = __byte_perm(a4.w, b4.w, 0x5410);
            dst[7] = __byte_perm(a4.w, b4.w, 0x7632);
        }
        __syncthreads();

        // ---- scores 128x64 (warp 32x32) ----
        {
            float sc[2][4][4];
            #pragma unroll
            for (int mi = 0; mi < 2; mi++)
                #pragma unroll
                for (int ni = 0; ni < 4; ni++)
                    #pragma unroll
                    for (int v = 0; v < 4; v++) sc[mi][ni][v] = 0.0f;

            #pragma unroll
            for (int kk = 0; kk < 8; kk++) {
                uint32_t afh[2][4], afl[2][4];
                #pragma unroll
                for (int mi = 0; mi < 2; mi++) {
                    int m0 = warpM * 32 + mi * 16;
                    afh[mi][0] = s.Qh[m0 + grp    ][kk * 8 + tk    ];
                    afh[mi][1] = s.Qh[m0 + grp + 8][kk * 8 + tk    ];
                    afh[mi][2] = s.Qh[m0 + grp    ][kk * 8 + tk + 4];
                    afh[mi][3] = s.Qh[m0 + grp + 8][kk * 8 + tk + 4];
                    afl[mi][0] = s.Ql[m0 + grp    ][kk * 8 + tk    ];
                    afl[mi][1] = s.Ql[m0 + grp + 8][kk * 8 + tk    ];
                    afl[mi][2] = s.Ql[m0 + grp    ][kk * 8 + tk + 4];
                    afl[mi][3] = s.Ql[m0 + grp + 8][kk * 8 + tk + 4];
                }
                #pragma unroll
                for (int ni = 0; ni < 4; ni++) {
                    int n0 = warpN * 32 + ni * 8;
                    uint32_t bfh[2], bfl[2];
                    bfh[0] = s.Kh[n0 + grp][kk * 8 + tk    ];
                    bfh[1] = s.Kh[n0 + grp][kk * 8 + tk + 4];
                    bfl[0] = s.Kl[n0 + grp][kk * 8 + tk    ];
                    bfl[1] = s.Kl[n0 + grp][kk * 8 + tk + 4];
                    #pragma unroll
                    for (int mi = 0; mi < 2; mi++) {
                        mma16(sc[mi][ni], afh[mi], bfh);
                        mma16(sc[mi][ni], afh[mi], bfl);
                        mma16(sc[mi][ni], afl[mi], bfh);
                    }
                }
            }
            #pragma unroll
            for (int mi = 0; mi < 2; mi++) {
                int rr = warpM * 32 + mi * 16 + grp;
                #pragma unroll
                for (int ni = 0; ni < 4; ni++) {
                    int cc = warpN * 32 + ni * 8 + tk * 2;
                    *(float2*)&s.S[rr][cc] =
                        make_float2(sc[mi][ni][0] * ATT_SCALE, sc[mi][ni][1] * ATT_SCALE);
                    *(float2*)&s.S[rr + 8][cc] =
                        make_float2(sc[mi][ni][2] * ATT_SCALE, sc[mi][ni][3] * ATT_SCALE);
                }
            }
        }
        __syncthreads();

        // ---- online softmax; P -> packed hi/lo ----
        {
            int rr = tid >> 1, c0 = (tid & 1) * 32;
            float mx = -1e30f;
            #pragma unroll
            for (int c = 0; c < 32; c++) mx = fmaxf(mx, s.S[rr][c0 + c]);
            mx = fmaxf(mx, __shfl_xor_sync(0xffffffffu, mx, 1));
            float mold = s.M[rr];
            float mnew = fmaxf(mold, mx);
            float ls = 0.0f;
            #pragma unroll
            for (int jp = 0; jp < 16; jp++) {
                float e0 = __expf(s.S[rr][c0 + 2 * jp    ] - mnew);
                float e1 = __expf(s.S[rr][c0 + 2 * jp + 1] - mnew);
                ls += e0 + e1;
                uint32_t hh, ll;
                cvt2(e0, e1, hh, ll);
                s.Ph[rr][c0 / 2 + jp] = hh;
                s.Pl[rr][c0 / 2 + jp] = ll;
            }
            ls += __shfl_xor_sync(0xffffffffu, ls, 1);
            if ((tid & 1) == 0) {
                float al = __expf(mold - mnew);
                s.M[rr] = mnew;
                s.Al[rr] = al;
                s.L[rr] = s.L[rr] * al + ls;
            }
        }
        __syncthreads();

        // ---- rescale + PV 128x128 (warp 32x64) ----
        {
            #pragma unroll
            for (int mi = 0; mi < 2; mi++) {
                int r0 = warpM * 32 + mi * 16 + grp;
                float a0 = s.Al[r0], a1 = s.Al[r0 + 8];
                #pragma unroll
                for (int ni = 0; ni < 8; ni++) {
                    o[mi][ni][0] *= a0; o[mi][ni][1] *= a0;
                    o[mi][ni][2] *= a1; o[mi][ni][3] *= a1;
                }
            }
            #pragma unroll
            for (int kk = 0; kk < 4; kk++) {
                uint32_t afh[2][4], afl[2][4];
                #pragma unroll
                for (int mi = 0; mi < 2; mi++) {
                    int m0 = warpM * 32 + mi * 16;
                    afh[mi][0] = s.Ph[m0 + grp    ][kk * 8 + tk    ];
                    afh[mi][1] = s.Ph[m0 + grp + 8][kk * 8 + tk    ];
                    afh[mi][2] = s.Ph[m0 + grp    ][kk * 8 + tk + 4];
                    afh[mi][3] = s.Ph[m0 + grp + 8][kk * 8 + tk + 4];
                    afl[mi][0] = s.Pl[m0 + grp    ][kk * 8 + tk    ];
                    afl[mi][1] = s.Pl[m0 + grp + 8][kk * 8 + tk    ];
                    afl[mi][2] = s.Pl[m0 + grp    ][kk * 8 + tk + 4];
                    afl[mi][3] = s.Pl[m0 + grp + 8][kk * 8 + tk + 4];
                }
                #pragma unroll
                for (int ni = 0; ni < 8; ni++) {
                    int n0 = warpN * 64 + ni * 8;
                    uint32_t bfh[2], bfl[2];
                    bfh[0] = s.Vh[kk * 8 + tk    ][n0 + grp];
                    bfh[1] = s.Vh[kk * 8 + tk + 4][n0 + grp];
                    bfl[0] = s.Vl[kk * 8 + tk    ][n0 + grp];
                    bfl[1] = s.Vl[kk * 8 + tk + 4][n0 + grp];
                    #pragma unroll
                    for (int mi = 0; mi < 2; mi++) {
                        mma16(o[mi][ni], afh[mi], bfh);
                        mma16(o[mi][ni], afh[mi], bfl);
                        mma16(o[mi][ni], afl[mi], bfh);
                    }
                }
            }
        }
        __syncthreads();
    }

    // ---- finalize: packed hi/lo output for the O GEMM ----
    #pragma unroll
    for (int mi = 0; mi < 2; mi++) {
        int r0 = warpM * 32 + mi * 16 + grp;
        float l0 = 1.0f / s.L[r0];
        float l1 = 1.0f / s.L[r0 + 8];
        int tok = b * SEQ + qt * 128;
        #pragma unroll
        for (int ni = 0; ni < 8; ni++) {
            int c = warpN * 64 + ni * 8 + tk * 2;
            int g = (c < HD) ? (colr + c) : (1024 + colr + (c - HD));
            int idx = g >> 1;
            uint32_t hh, ll;
            cvt2(o[mi][ni][0] * l0, o[mi][ni][1] * l0, hh, ll);
            Aoh[(size_t)(tok + r0) * KP + idx] = hh;
            Aol[(size_t)(tok + r0) * KP + idx] = ll;
            cvt2(o[mi][ni][2] * l1, o[mi][ni][3] * l1, hh, ll);
            Aoh[(size_t)(tok + r0 + 8) * KP + idx] = hh;
            Aol[(size_t)(tok + r0 + 8) * KP + idx] = ll;
        }
    }
}

// ---------------------------------------------------------------------------
extern "C" void kernel_launch(void* const* d_in, const int* in_sizes, int n_in,
                              void* d_out, int out_size)
{
    const float* zr   = (const float*)d_in[0];
    const float* zi   = (const float*)d_in[1];
    const float* wq_r = (const float*)d_in[2];
    const float* wq_i = (const float*)d_in[3];
    const float* wk_r = (const float*)d_in[4];
    const float* wk_i = (const float*)d_in[5];
    const float* wv_r = (const float*)d_in[6];
    const float* wv_i = (const float*)d_in[7];
    const float* wo_r = (const float*)d_in[8];
    const float* wo_i = (const float*)d_in[9];

    uint32_t* sc = nullptr;
    cudaGetSymbolAddress((void**)&sc, g_scratch);
    uint32_t* Azh = sc + 0u  * MEGA;
    uint32_t* Azl = sc + 4u  * MEGA;
    uint32_t* Bqh = sc + 8u  * MEGA;  uint32_t* Bql = sc + 10u * MEGA;
    uint32_t* Bkh = sc + 12u * MEGA;  uint32_t* Bkl = sc + 14u * MEGA;
    uint32_t* Bvh = sc + 16u * MEGA;  uint32_t* Bvl = sc + 18u * MEGA;
    uint32_t* Boh = sc + 20u * MEGA;  uint32_t* Bol = sc + 22u * MEGA;
    uint32_t* Qh  = sc + 24u * MEGA;  uint32_t* Ql  = sc + 28u * MEGA;
    uint32_t* Kh  = sc + 32u * MEGA;  uint32_t* Kl  = sc + 36u * MEGA;
    uint32_t* Vh  = sc + 40u * MEGA;  uint32_t* Vl  = sc + 44u * MEGA;
    uint32_t* Aoh = sc + 48u * MEGA;  uint32_t* Aol = sc + 52u * MEGA;

    float* yr = (float*)d_out;
    float* yi = (float*)d_out + NTD;

    pack_x<<<(NTOK * KP) / 256, 256>>>(zr, zi, Azh, Azl);
    pack_w<<<(KP * 2048) / 256, 256>>>(wq_r, wq_i, Bqh, Bql);
    pack_w<<<(KP * 2048) / 256, 256>>>(wk_r, wk_i, Bkh, Bkl);
    pack_w<<<(KP * 2048) / 256, 256>>>(wv_r, wv_i, Bvh, Bvl);
    pack_w<<<(KP * 2048) / 256, 256>>>(wo_r, wo_i, Boh, Bol);

    dim3 ggrid(2048 / 128, NTOK / 128);     // (16, 32)
    gemm_bf16x3<<<ggrid, 128>>>(Azh, Azl, Bqh, Bql, Qh, Ql, nullptr, nullptr, 1);
    gemm_bf16x3<<<ggrid, 128>>>(Azh, Azl, Bkh, Bkl, Kh, Kl, nullptr, nullptr, 1);
    gemm_bf16x3<<<ggrid, 128>>>(Azh, Azl, Bvh, Bvl, Vh, Vl, nullptr, nullptr, 1);

    static const int kSmem = (int)sizeof(FSmem);
    cudaFuncSetAttribute(flash_bf16x3, cudaFuncAttributeMaxDynamicSharedMemorySize, kSmem);
    dim3 fgrid(SEQ / 128, BATCH * NH);      // (16, 32)
    flash_bf16x3<<<fgrid, 256, kSmem>>>(Qh, Ql, Kh, Kl, Vh, Vl, Aoh, Aol);

    gemm_bf16x3<<<ggrid, 128>>>(Aoh, Aol, Boh, Bol, nullptr, nullptr, yr, yi, 0);
}